// round 4
// baseline (speedup 1.0000x reference)
#include <cuda_runtime.h>
#include <cstdint>

#define N_NODES 100000
#define CH      128
#define N_REL   16
#define N_EDGES 200000
#define NW      (1 + N_REL)          /* 17 weight matrices (self + rels) */
#define NG      ((N_NODES + 127) / 128)   /* 782 gemm blocks */
#define NSCAT   1184                 /* scatter blocks (grid-stride) */

// ---------------- device scratch (no allocations allowed) ----------------
__device__ float          g_y[2][(size_t)N_NODES * CH];      // 2 x 51.2 MB ping-pong
__device__ int            g_idx32[N_REL * 2 * N_EDGES];      // 25.6 MB
__device__ unsigned char  g_mask[N_REL * N_EDGES];           // 3.2 MB
__device__ int            g_deg[N_REL * N_NODES];            // 6.4 MB
__device__ float          g_invdeg[N_REL * N_NODES];         // 6.4 MB
__device__ float          g_B[NW * CH * CH];                 // 1.1 MB (tf32-rounded weights)
__device__ int            g_flags[2];                        // [0]=idx is int64, [1]=mask is int32

// ---------------- dtype detection (jax int64/bool layout may vary) -------
__global__ void k_detect(const unsigned int* __restrict__ w,
                         const unsigned char* __restrict__ mb) {
    __shared__ int s64, s32;
    if (threadIdx.x == 0) { s64 = 0; s32 = 0; }
    __syncthreads();
    if (threadIdx.x < 128) {
        if (w[2 * threadIdx.x + 1] != 0u) atomicAdd(&s64, 1);
    }
    if (threadIdx.x < 192) {
        int i = (threadIdx.x / 3) * 4 + 1 + (threadIdx.x % 3);
        if (mb[i] != 0) atomicAdd(&s32, 1);
    }
    __syncthreads();
    if (threadIdx.x == 0) {
        g_flags[0] = (s64 < 8);
        g_flags[1] = (s32 < 8);
    }
}

__global__ void k_cvt_idx(const void* __restrict__ p) {
    int i = blockIdx.x * blockDim.x + threadIdx.x;
    if (i >= N_REL * 2 * N_EDGES) return;
    if (g_flags[0]) g_idx32[i] = (int)((const long long*)p)[i];
    else            g_idx32[i] = ((const int*)p)[i];
}

__global__ void k_cvt_mask(const void* __restrict__ p) {
    int i = blockIdx.x * blockDim.x + threadIdx.x;
    if (i >= N_REL * N_EDGES) return;
    if (g_flags[1]) g_mask[i] = (((const int*)p)[i] != 0);
    else            g_mask[i] = ((const unsigned char*)p)[i];
}

// ---------------- degree ----------------
__global__ void k_zero_deg() {
    int i = blockIdx.x * blockDim.x + threadIdx.x;
    if (i < N_REL * N_NODES) g_deg[i] = 0;
}

__global__ void k_deg() {
    int e = blockIdx.x * blockDim.x + threadIdx.x;
    int rel = blockIdx.y;
    if (e >= N_EDGES) return;
    if (!g_mask[rel * N_EDGES + e]) return;
    int dst = g_idx32[rel * 2 * N_EDGES + N_EDGES + e];
    atomicAdd(&g_deg[rel * N_NODES + dst], 1);
}

__global__ void k_invdeg() {
    int i = blockIdx.x * blockDim.x + threadIdx.x;
    if (i >= N_REL * N_NODES) return;
    int d = g_deg[i];
    g_invdeg[i] = d > 0 ? 1.0f / (float)d : 0.0f;
}

// ---------------- round weights to tf32 (removes truncation bias) -------
__device__ __forceinline__ unsigned f2tf(float f) {
    unsigned r;
    asm("cvt.rna.tf32.f32 %0, %1;" : "=r"(r) : "f"(f));
    return r;
}

__global__ void k_roundB(const float* __restrict__ selfw, const float* __restrict__ relw) {
    int i = blockIdx.x * blockDim.x + threadIdx.x;
    if (i >= NW * CH * CH) return;
    float v = (i < CH * CH) ? selfw[i] : relw[i - CH * CH];
    g_B[i] = __uint_as_float(f2tf(v));
}

// ---------------- GEMM block: out[128 rows] = x_tile @ Bw  (tf32 mma) ---
#define AS 36    /* A smem row stride (floats) */
#define BS 136   /* B smem row stride */
#define SMEM_FLOATS (2 * 128 * AS + 2 * 32 * BS)

__device__ __forceinline__ void cp16(float* sdst, const float* gsrc, int bytes) {
    unsigned s = (unsigned)__cvta_generic_to_shared(sdst);
    asm volatile("cp.async.cg.shared.global [%0], [%1], 16, %2;\n"
                 :: "r"(s), "l"(gsrc), "r"(bytes));
}

__device__ void gemm_block(const float* __restrict__ x, const float* __restrict__ Bw,
                           float* __restrict__ outp, int bid, float* sm) {
    float* sA = sm;
    float* sB = sm + 2 * 128 * AS;
    int tid = threadIdx.x;
    int warp = tid >> 5, lane = tid & 31;
    int wm = warp >> 2, wn = warp & 3;   // 2x4 warp grid, warp tile 64x32
    int bM = bid * 128;

    float c[4][4][4];
#pragma unroll
    for (int i = 0; i < 4; i++)
#pragma unroll
        for (int j = 0; j < 4; j++)
#pragma unroll
            for (int k = 0; k < 4; k++) c[i][j][k] = 0.f;

    const int NK = CH / 32;   // 4

    auto load_stage = [&](int kt, int stage) {
        float* dA = sA + stage * 128 * AS;
        float* dB = sB + stage * 32 * BS;
#pragma unroll
        for (int i = 0; i < 4; i++) {
            int idx = tid + 256 * i;
            int row = idx >> 3, c4 = idx & 7;     // A tile 128 x 8 float4
            int rg = bM + row;
            const float* src = x + (size_t)rg * CH + kt * 32 + c4 * 4;
            int ok = (rg < N_NODES) ? 16 : 0;
            cp16(dA + row * AS + c4 * 4, ok ? src : x, ok);
        }
#pragma unroll
        for (int i = 0; i < 4; i++) {
            int idx = tid + 256 * i;
            int kr = idx >> 5, c4 = idx & 31;     // B tile 32 x 32 float4
            cp16(dB + kr * BS + c4 * 4, Bw + (size_t)(kt * 32 + kr) * CH + c4 * 4, 16);
        }
        asm volatile("cp.async.commit_group;\n");
    };

    load_stage(0, 0);

    for (int kt = 0; kt < NK; kt++) {
        int stage = kt & 1;
        if (kt + 1 < NK) {
            load_stage(kt + 1, stage ^ 1);
            asm volatile("cp.async.wait_group 1;\n");
        } else {
            asm volatile("cp.async.wait_group 0;\n");
        }
        __syncthreads();

        const float* A = sA + stage * 128 * AS + (wm * 64) * AS;
        const float* B = sB + stage * 32 * BS + wn * 32;
#pragma unroll
        for (int ks = 0; ks < 4; ks++) {
            unsigned a[4][4], b[4][2];
            int col = ks * 8 + (lane & 3);
            int r = (lane >> 2);
#pragma unroll
            for (int mf = 0; mf < 4; mf++) {
                const float* Ap = A + (mf * 16 + r) * AS + col;
                a[mf][0] = f2tf(Ap[0]);
                a[mf][1] = f2tf(Ap[8 * AS]);
                a[mf][2] = f2tf(Ap[4]);
                a[mf][3] = f2tf(Ap[8 * AS + 4]);
            }
            int kr = ks * 8 + (lane & 3);
#pragma unroll
            for (int nf = 0; nf < 4; nf++) {
                const float* Bp = B + kr * BS + nf * 8 + (lane >> 2);
                b[nf][0] = __float_as_uint(Bp[0]);       // g_B pre-rounded to tf32
                b[nf][1] = __float_as_uint(Bp[4 * BS]);
            }
#pragma unroll
            for (int mf = 0; mf < 4; mf++)
#pragma unroll
                for (int nf = 0; nf < 4; nf++)
                    asm volatile(
                        "mma.sync.aligned.m16n8k8.row.col.f32.tf32.tf32.f32 "
                        "{%0,%1,%2,%3},{%4,%5,%6,%7},{%8,%9},{%0,%1,%2,%3};\n"
                        : "+f"(c[mf][nf][0]), "+f"(c[mf][nf][1]),
                          "+f"(c[mf][nf][2]), "+f"(c[mf][nf][3])
                        : "r"(a[mf][0]), "r"(a[mf][1]), "r"(a[mf][2]), "r"(a[mf][3]),
                          "r"(b[nf][0]), "r"(b[nf][1]));
        }
        __syncthreads();
    }

#pragma unroll
    for (int mf = 0; mf < 4; mf++) {
        int r0 = bM + wm * 64 + mf * 16 + (lane >> 2);
#pragma unroll
        for (int nf = 0; nf < 4; nf++) {
            int cc = wn * 32 + nf * 8 + (lane & 3) * 2;
            if (r0 < N_NODES)
                *(float2*)(outp + (size_t)r0 * CH + cc) = make_float2(c[mf][nf][0], c[mf][nf][1]);
            if (r0 + 8 < N_NODES)
                *(float2*)(outp + (size_t)(r0 + 8) * CH + cc) = make_float2(c[mf][nf][2], c[mf][nf][3]);
        }
    }
}

// ---------------- scatter block: out[dst] += y[src] * invdeg ------------
__device__ void scatter_block(const float* __restrict__ y, float* __restrict__ out,
                              int rel, int sbid) {
    int warp = threadIdx.x >> 5, lane = threadIdx.x & 31;
    const int* ip = g_idx32 + rel * 2 * N_EDGES;
    const unsigned char* mp = g_mask + rel * N_EDGES;
    const float* vp = g_invdeg + rel * N_NODES;
    for (int e = sbid * 8 + warp; e < N_EDGES; e += NSCAT * 8) {
        if (!mp[e]) continue;
        int src = ip[e];
        int dst = ip[N_EDGES + e];
        float s = vp[dst];
        float4 v = __ldg((const float4*)(y + (size_t)src * CH) + lane);
        float4* a = (float4*)(out + (size_t)dst * CH) + lane;
        atomicAdd(a, make_float4(v.x * s, v.y * s, v.z * s, v.w * s));  // RED.V4, no return
    }
}

// ---------------- fused step: up to 2 gemm segments + 1 scatter segment --
__global__ __launch_bounds__(256, 2) void k_step(
    const float* __restrict__ x, float* __restrict__ out,
    int n1, int g1, float* o1,
    int n2, int g2, float* o2,
    int srel, const float* ysrc) {
    extern __shared__ float sm[];
    int bid = blockIdx.x;
    if (bid < n1)            gemm_block(x, g_B + (size_t)g1 * CH * CH, o1, bid, sm);
    else if (bid < n1 + n2)  gemm_block(x, g_B + (size_t)g2 * CH * CH, o2, bid - n1, sm);
    else                     scatter_block(ysrc, out, srel, bid - n1 - n2);
}

// ---------------- launch ----------------
extern "C" void kernel_launch(void* const* d_in, const int* in_sizes, int n_in,
                              void* d_out, int out_size) {
    const float* x     = (const float*)d_in[0];
    const void*  idx   = d_in[1];
    const void*  mask  = d_in[2];
    const float* selfw = (const float*)d_in[3];
    const float* relw  = (const float*)d_in[4];
    float* out = (float*)d_out;

    static float* yptr[2] = {nullptr, nullptr};
    static int init = 0;
    size_t smem = SMEM_FLOATS * sizeof(float);   // 71680 B
    if (!init) {
        cudaFuncSetAttribute(k_step, cudaFuncAttributeMaxDynamicSharedMemorySize, (int)smem);
        void* p;
        cudaGetSymbolAddress(&p, g_y);
        yptr[0] = (float*)p;
        yptr[1] = (float*)p + (size_t)N_NODES * CH;
        init = 1;
    }

    k_detect<<<1, 256>>>((const unsigned int*)idx, (const unsigned char*)mask);
    k_cvt_idx<<<(N_REL * 2 * N_EDGES + 255) / 256, 256>>>(idx);
    k_cvt_mask<<<(N_REL * N_EDGES + 255) / 256, 256>>>(mask);
    k_zero_deg<<<(N_REL * N_NODES + 255) / 256, 256>>>();
    k_deg<<<dim3((N_EDGES + 255) / 256, N_REL), 256>>>();
    k_invdeg<<<(N_REL * N_NODES + 255) / 256, 256>>>();
    k_roundB<<<(NW * CH * CH + 255) / 256, 256>>>(selfw, relw);

    // step 0: self gemm -> out, rel0 gemm -> y0 (no scatter yet)
    k_step<<<2 * NG, 256, smem>>>(x, out, NG, 0, out, NG, 1, yptr[0], -1, nullptr);

    // steps 1..15: gemm rel r -> y[r&1], concurrently scatter rel r-1 from y[(r-1)&1]
    for (int r = 1; r < N_REL; r++) {
        k_step<<<NG + NSCAT, 256, smem>>>(x, out,
                                          NG, r + 1, yptr[r & 1],
                                          0, 0, nullptr,
                                          r - 1, yptr[(r - 1) & 1]);
    }

    // final: scatter rel 15 from y[1]
    k_step<<<NSCAT, 256, smem>>>(x, out, 0, 0, nullptr, 0, 0, nullptr,
                                 N_REL - 1, yptr[(N_REL - 1) & 1]);
}

// round 5
// speedup vs baseline: 1.7354x; 1.7354x over previous
#include <cuda_runtime.h>
#include <cstdint>

#define N_NODES 100000
#define CH      128
#define N_REL   16
#define N_EDGES 200000
#define NW      17                       /* self + 16 relations */
#define NT      ((N_NODES + 127) / 128)  /* 782 dst tiles */
#define NBK     (NT * N_REL * 8)         /* 100096 buckets (tile,rel,warp) */
#define HS      132                      /* h row stride (floats) */
#define BS      136                      /* B smem row stride */
#define HSZ     (128 * HS)

// ---------------- device scratch ----------------
__device__ unsigned      g_emeta[N_REL * N_EDGES];   // 12.8 MB  src|dl<<17
__device__ int           g_idx32[N_REL * 2 * N_EDGES];
__device__ unsigned char g_mask[N_REL * N_EDGES];
__device__ int           g_deg[N_REL * N_NODES];
__device__ float         g_invdeg[N_REL * N_NODES];
__device__ float         g_B[NW * CH * CH];          // tf32-rounded weights
__device__ int           g_bcnt[NBK];
__device__ int           g_boff[NBK + 1];
__device__ int           g_bfill[NBK];
__device__ int           g_bsum[128];
__device__ int           g_flags[2];

// ---------------- dtype detection ----------------
__global__ void k_detect(const unsigned* __restrict__ w, const unsigned char* __restrict__ mb) {
    __shared__ int s64, s32;
    if (threadIdx.x == 0) { s64 = 0; s32 = 0; }
    __syncthreads();
    if (threadIdx.x < 128) { if (w[2 * threadIdx.x + 1] != 0u) atomicAdd(&s64, 1); }
    if (threadIdx.x < 192) {
        int i = (threadIdx.x / 3) * 4 + 1 + (threadIdx.x % 3);
        if (mb[i] != 0) atomicAdd(&s32, 1);
    }
    __syncthreads();
    if (threadIdx.x == 0) { g_flags[0] = (s64 < 8); g_flags[1] = (s32 < 8); }
}

__global__ void k_cvt_idx(const void* __restrict__ p) {
    int i = blockIdx.x * blockDim.x + threadIdx.x;
    if (i >= N_REL * 2 * N_EDGES) return;
    if (g_flags[0]) g_idx32[i] = (int)((const long long*)p)[i];
    else            g_idx32[i] = ((const int*)p)[i];
}

__global__ void k_cvt_mask(const void* __restrict__ p) {
    int i = blockIdx.x * blockDim.x + threadIdx.x;
    if (i >= N_REL * N_EDGES) return;
    if (g_flags[1]) g_mask[i] = (((const int*)p)[i] != 0);
    else            g_mask[i] = ((const unsigned char*)p)[i];
}

// ---------------- zero deg + bucket counts ----------------
__global__ void k_zero_pre() {
    int stride = gridDim.x * blockDim.x;
    for (int i = blockIdx.x * blockDim.x + threadIdx.x; i < N_REL * N_NODES; i += stride)
        g_deg[i] = 0;
    for (int i = blockIdx.x * blockDim.x + threadIdx.x; i < NBK; i += stride)
        g_bcnt[i] = 0;
}

// ---------------- degree + bucket counting ----------------
__global__ void k_deg() {
    int e = blockIdx.x * blockDim.x + threadIdx.x;
    int rel = blockIdx.y;
    if (e >= N_EDGES) return;
    if (!g_mask[rel * N_EDGES + e]) return;
    int dst = g_idx32[rel * 2 * N_EDGES + N_EDGES + e];
    atomicAdd(&g_deg[rel * N_NODES + dst], 1);
    int key = (dst >> 7) * 128 + rel * 8 + ((dst >> 4) & 7);
    atomicAdd(&g_bcnt[key], 1);
}

__global__ void k_invdeg() {
    int i = blockIdx.x * blockDim.x + threadIdx.x;
    if (i >= N_REL * N_NODES) return;
    int d = g_deg[i];
    g_invdeg[i] = d > 0 ? 1.0f / (float)d : 0.0f;
}

// ---------------- prefix scan of bucket counts (3 tiny kernels) ----------
__global__ void k_scan1() {
    __shared__ int sh[1024];
    int i = blockIdx.x * 1024 + threadIdx.x;
    int v = (i < NBK) ? g_bcnt[i] : 0;
    sh[threadIdx.x] = v;
    __syncthreads();
    for (int off = 1; off < 1024; off <<= 1) {
        int t = (threadIdx.x >= off) ? sh[threadIdx.x - off] : 0;
        __syncthreads();
        sh[threadIdx.x] += t;
        __syncthreads();
    }
    if (i < NBK) g_boff[i] = sh[threadIdx.x] - v;      // exclusive
    if (threadIdx.x == 1023) g_bsum[blockIdx.x] = sh[1023];
}

__global__ void k_scan2(int nb) {
    __shared__ int sh[128];
    int v = (threadIdx.x < nb) ? g_bsum[threadIdx.x] : 0;
    sh[threadIdx.x] = v;
    __syncthreads();
    for (int off = 1; off < 128; off <<= 1) {
        int t = (threadIdx.x >= off) ? sh[threadIdx.x - off] : 0;
        __syncthreads();
        sh[threadIdx.x] += t;
        __syncthreads();
    }
    if (threadIdx.x < nb) g_bsum[threadIdx.x] = sh[threadIdx.x] - v;  // exclusive
    if (threadIdx.x == 127) g_boff[NBK] = sh[127];                    // total
}

__global__ void k_scan3() {
    int i = blockIdx.x * 1024 + threadIdx.x;
    if (i >= NBK) return;
    int o = g_boff[i] + g_bsum[blockIdx.x];
    g_boff[i] = o;
    g_bfill[i] = o;
}

// ---------------- fill edge meta (counting sort) ----------------
__global__ void k_fill() {
    int e = blockIdx.x * blockDim.x + threadIdx.x;
    int rel = blockIdx.y;
    if (e >= N_EDGES) return;
    if (!g_mask[rel * N_EDGES + e]) return;
    const int* ip = g_idx32 + rel * 2 * N_EDGES;
    int src = ip[e];
    int dst = ip[N_EDGES + e];
    int key = (dst >> 7) * 128 + rel * 8 + ((dst >> 4) & 7);
    int pos = atomicAdd(&g_bfill[key], 1);
    g_emeta[pos] = (unsigned)src | ((unsigned)(dst & 127) << 17);
}

// ---------------- tf32-round weights ----------------
__device__ __forceinline__ unsigned f2tf(float f) {
    unsigned r;
    asm("cvt.rna.tf32.f32 %0, %1;" : "=r"(r) : "f"(f));
    return r;
}

__global__ void k_roundB(const float* __restrict__ selfw, const float* __restrict__ relw) {
    int i = blockIdx.x * blockDim.x + threadIdx.x;
    if (i >= NW * CH * CH) return;
    float v = (i < CH * CH) ? selfw[i] : relw[i - CH * CH];
    g_B[i] = __uint_as_float(f2tf(v));
}

// ---------------- fused kernel helpers ----------------
__device__ __forceinline__ void cp16(float* sdst, const float* gsrc) {
    unsigned s = (unsigned)__cvta_generic_to_shared(sdst);
    asm volatile("cp.async.cg.shared.global [%0], [%1], 16;\n" :: "r"(s), "l"(gsrc));
}

__device__ __forceinline__ void cp_stage(float* sB, int s, int tid) {
    if (s > 4 * NW - 1) return;
    int w = s >> 2, kt = s & 3;
    float* dB = sB + (s % 3) * 32 * BS;
    const float* src0 = g_B + (size_t)w * CH * CH + kt * 32 * CH;
#pragma unroll
    for (int i = 0; i < 4; i++) {
        int idx = tid + 256 * i;
        int kr = idx >> 5, c4 = idx & 31;
        cp16(dB + kr * BS + c4 * 4, src0 + kr * CH + c4 * 4);
    }
}

__device__ __forceinline__ void mma4(float (*c)[4][4], const float* A, const float* Bsm,
                                     int kt, int lane) {
#pragma unroll
    for (int ks = 0; ks < 4; ks++) {
        unsigned a[4][4], b[4][2];
        int col = kt * 32 + ks * 8 + (lane & 3);
        int r = lane >> 2;
#pragma unroll
        for (int mf = 0; mf < 4; mf++) {
            const float* Ap = A + (mf * 16 + r) * HS + col;
            a[mf][0] = f2tf(Ap[0]);
            a[mf][1] = f2tf(Ap[8 * HS]);
            a[mf][2] = f2tf(Ap[4]);
            a[mf][3] = f2tf(Ap[8 * HS + 4]);
        }
        int kr = ks * 8 + (lane & 3);
#pragma unroll
        for (int nf = 0; nf < 4; nf++) {
            const float* Bp = Bsm + kr * BS + nf * 8 + (lane >> 2);
            b[nf][0] = __float_as_uint(Bp[0]);      // pre-rounded tf32
            b[nf][1] = __float_as_uint(Bp[4 * BS]);
        }
#pragma unroll
        for (int mf = 0; mf < 4; mf++)
#pragma unroll
            for (int nf = 0; nf < 4; nf++)
                asm volatile(
                    "mma.sync.aligned.m16n8k8.row.col.f32.tf32.tf32.f32 "
                    "{%0,%1,%2,%3},{%4,%5,%6,%7},{%8,%9},{%0,%1,%2,%3};\n"
                    : "+f"(c[mf][nf][0]), "+f"(c[mf][nf][1]),
                      "+f"(c[mf][nf][2]), "+f"(c[mf][nf][3])
                    : "r"(a[mf][0]), "r"(a[mf][1]), "r"(a[mf][2]), "r"(a[mf][3]),
                      "r"(b[nf][0]), "r"(b[nf][1]));
    }
}

// per-warp gather: h rows [wid*16, wid*16+16) = Σ x[src]·invdeg  (no atomics)
__device__ __forceinline__ void gather_rel(const float* __restrict__ x, float* hb,
                                           int tile, int rel, int wid, int lane) {
    float4 z = make_float4(0.f, 0.f, 0.f, 0.f);
    int r0 = wid * 16;
#pragma unroll
    for (int r = 0; r < 16; r++)
        ((float4*)(hb + (r0 + r) * HS))[lane] = z;

    int key = tile * 128 + rel * 8 + wid;
    int beg = g_boff[key], end = g_boff[key + 1];
    const float* vd = g_invdeg + rel * N_NODES + tile * 128;
    for (int base = beg; base < end; base += 32) {
        unsigned m = 0;
        if (base + lane < end) m = g_emeta[base + lane];
        int n = min(32, end - base);
        for (int j = 0; j < n; j++) {
            unsigned u = __shfl_sync(0xffffffffu, m, j);
            int srcn = (int)(u & 0x1FFFFu);
            int dl = (int)(u >> 17);
            float s = __ldg(vd + dl);
            float4 v = __ldg((const float4*)(x + (size_t)srcn * CH) + lane);
            float4* hp = (float4*)(hb + dl * HS) + lane;
            float4 hv = *hp;
            hv.x += v.x * s; hv.y += v.y * s; hv.z += v.z * s; hv.w += v.w * s;
            *hp = hv;
        }
    }
}

// ---------------- fused: per dst-tile, 17x (build A-tile, mma), store once
__global__ __launch_bounds__(256, 1) void k_fused(const float* __restrict__ x,
                                                  float* __restrict__ out) {
    extern __shared__ float sm[];
    float* h  = sm;               // 2 * HSZ
    float* sB = sm + 2 * HSZ;     // 3 * 32 * BS
    int tid = threadIdx.x, wid = tid >> 5, lane = tid & 31;
    int wm = wid >> 2, wn = wid & 3;
    int tile = blockIdx.x, bM = tile * 128;

    // self A-tile (w=0) = x rows, into h[0]
    {
        int r0 = wid * 16;
#pragma unroll
        for (int r = 0; r < 16; r++) {
            int rg = bM + r0 + r;
            float4 v = make_float4(0.f, 0.f, 0.f, 0.f);
            if (rg < N_NODES) v = __ldg((const float4*)(x + (size_t)rg * CH) + lane);
            ((float4*)(h + (r0 + r) * HS))[lane] = v;
        }
    }
    cp_stage(sB, 0, tid);
    asm volatile("cp.async.commit_group;\n");
    cp_stage(sB, 1, tid);
    asm volatile("cp.async.commit_group;\n");

    float c[4][4][4];
#pragma unroll
    for (int i = 0; i < 4; i++)
#pragma unroll
        for (int j = 0; j < 4; j++)
#pragma unroll
            for (int k = 0; k < 4; k++) c[i][j][k] = 0.f;

#pragma unroll 1
    for (int s = 0; s < 4 * NW; s++) {
        int w = s >> 2, kt = s & 3;
        if (s < 4 * NW - 1) asm volatile("cp.async.wait_group 1;\n");
        else                asm volatile("cp.async.wait_group 0;\n");
        __syncthreads();
        // safe: buffer (s+2)%3's readers were mma(s-1), all before this barrier
        cp_stage(sB, s + 2, tid);
        asm volatile("cp.async.commit_group;\n");

        const float* A   = h + (w & 1) * HSZ + (wm * 64) * HS;
        const float* Bsm = sB + (s % 3) * 32 * BS + wn * 32;
        mma4(c, A, Bsm, kt, lane);

        if (kt == 3 && w < NW - 1)
            gather_rel(x, h + ((w + 1) & 1) * HSZ, tile, w /*rel*/, wid, lane);
    }

    // epilogue: single non-atomic store
#pragma unroll
    for (int mf = 0; mf < 4; mf++) {
        int r0 = bM + wm * 64 + mf * 16 + (lane >> 2);
#pragma unroll
        for (int nf = 0; nf < 4; nf++) {
            int cc = wn * 32 + nf * 8 + (lane & 3) * 2;
            if (r0 < N_NODES)
                *(float2*)(out + (size_t)r0 * CH + cc) = make_float2(c[mf][nf][0], c[mf][nf][1]);
            if (r0 + 8 < N_NODES)
                *(float2*)(out + (size_t)(r0 + 8) * CH + cc) = make_float2(c[mf][nf][2], c[mf][nf][3]);
        }
    }
}

// ---------------- launch ----------------
extern "C" void kernel_launch(void* const* d_in, const int* in_sizes, int n_in,
                              void* d_out, int out_size) {
    const float* x     = (const float*)d_in[0];
    const void*  idx   = d_in[1];
    const void*  mask  = d_in[2];
    const float* selfw = (const float*)d_in[3];
    const float* relw  = (const float*)d_in[4];
    float* out = (float*)d_out;

    static int init = 0;
    size_t smem = (2 * HSZ + 3 * 32 * BS) * sizeof(float);   // 187392 B
    if (!init) {
        cudaFuncSetAttribute(k_fused, cudaFuncAttributeMaxDynamicSharedMemorySize, (int)smem);
        init = 1;
    }

    int nb1 = (NBK + 1023) / 1024;   // 98

    k_detect<<<1, 256>>>((const unsigned*)idx, (const unsigned char*)mask);
    k_cvt_idx<<<(N_REL * 2 * N_EDGES + 255) / 256, 256>>>(idx);
    k_cvt_mask<<<(N_REL * N_EDGES + 255) / 256, 256>>>(mask);
    k_zero_pre<<<2048, 256>>>();
    k_roundB<<<(NW * CH * CH + 255) / 256, 256>>>(selfw, relw);
    k_deg<<<dim3((N_EDGES + 255) / 256, N_REL), 256>>>();
    k_invdeg<<<(N_REL * N_NODES + 255) / 256, 256>>>();
    k_scan1<<<nb1, 1024>>>();
    k_scan2<<<1, 128>>>(nb1);
    k_scan3<<<nb1, 1024>>>();
    k_fill<<<dim3((N_EDGES + 255) / 256, N_REL), 256>>>();
    k_fused<<<NT, 256, smem>>>(x, out);
}

// round 7
// speedup vs baseline: 2.7032x; 1.5577x over previous
#include <cuda_runtime.h>
#include <cstdint>

#define N_NODES 100000
#define CH      128
#define N_REL   16
#define N_EDGES 200000
#define NW      17                        /* self + 16 relations */
#define NT      ((N_NODES + 127) / 128)   /* 782 dst tiles */
#define NBK     (NT * N_REL * 8)          /* 100096 buckets (tile,rel,gwarp) */
#define HS      132                       /* hA row stride (floats) */
#define BS      136                       /* B smem row stride (floats) */
#define HSZ     (128 * HS)                /* floats per hA buffer */

// smem: hA0 | hA1 | B-ring(3 x 32*BS)
#define SMF_HA0  0
#define SMF_HA1  HSZ
#define SMF_B    (2 * HSZ)
#define SMEM_FLOATS (2 * HSZ + 3 * 32 * BS)
#define NSTG     (4 * NW)                 /* 68 B k-chunks */

// ---------------- device scratch ----------------
__device__ unsigned      g_emeta[N_REL * N_EDGES];   // src | dl<<17 (sorted by bucket)
__device__ float         g_B[NW * CH * CH];          // tf32-rounded weights
__device__ int           g_deg[N_REL * N_NODES];
__device__ float         g_invdeg[N_REL * N_NODES];
__device__ int           g_bcnt[NBK];
__device__ int           g_boff[NBK + 1];
__device__ int           g_bfill[NBK];
__device__ int           g_bsum[128];
__device__ int           g_flags[2];

// ---------------- dtype detection (jax int64/bool layout may vary) -------
__global__ void k_detect(const unsigned* __restrict__ w, const unsigned char* __restrict__ mb) {
    __shared__ int s64, s32;
    if (threadIdx.x == 0) { s64 = 0; s32 = 0; }
    __syncthreads();
    if (threadIdx.x < 128) { if (w[2 * threadIdx.x + 1] != 0u) atomicAdd(&s64, 1); }
    if (threadIdx.x < 192) {
        int i = (threadIdx.x / 3) * 4 + 1 + (threadIdx.x % 3);
        if (mb[i] != 0) atomicAdd(&s32, 1);
    }
    __syncthreads();
    if (threadIdx.x == 0) { g_flags[0] = (s64 < 8); g_flags[1] = (s32 < 8); }
}

__device__ __forceinline__ int rd_idx(const void* p, int i) {
    return g_flags[0] ? (int)((const long long*)p)[i] : ((const int*)p)[i];
}
__device__ __forceinline__ int rd_mask(const void* p, int i) {
    return g_flags[1] ? (((const int*)p)[i] != 0) : (int)((const unsigned char*)p)[i];
}

// ---------------- zero ----------------
__global__ void k_zero_pre() {
    int stride = gridDim.x * blockDim.x;
    for (int i = blockIdx.x * blockDim.x + threadIdx.x; i < N_REL * N_NODES; i += stride)
        g_deg[i] = 0;
    for (int i = blockIdx.x * blockDim.x + threadIdx.x; i < NBK; i += stride)
        g_bcnt[i] = 0;
}

// ---------------- degree + bucket counting ----------------
__global__ void k_deg(const void* __restrict__ idx, const void* __restrict__ mask) {
    int e = blockIdx.x * blockDim.x + threadIdx.x;
    int rel = blockIdx.y;
    if (e >= N_EDGES) return;
    if (!rd_mask(mask, rel * N_EDGES + e)) return;
    int dst = rd_idx(idx, rel * 2 * N_EDGES + N_EDGES + e);
    atomicAdd(&g_deg[rel * N_NODES + dst], 1);
    int key = (dst >> 7) * 128 + rel * 8 + ((dst >> 4) & 7);
    atomicAdd(&g_bcnt[key], 1);
}

__global__ void k_invdeg() {
    int i = blockIdx.x * blockDim.x + threadIdx.x;
    if (i >= N_REL * N_NODES) return;
    int d = g_deg[i];
    g_invdeg[i] = d > 0 ? 1.0f / (float)d : 0.0f;
}

// ---------------- prefix scan ----------------
__global__ void k_scan1() {
    __shared__ int sh[1024];
    int i = blockIdx.x * 1024 + threadIdx.x;
    int v = (i < NBK) ? g_bcnt[i] : 0;
    sh[threadIdx.x] = v;
    __syncthreads();
    for (int off = 1; off < 1024; off <<= 1) {
        int t = (threadIdx.x >= off) ? sh[threadIdx.x - off] : 0;
        __syncthreads();
        sh[threadIdx.x] += t;
        __syncthreads();
    }
    if (i < NBK) g_boff[i] = sh[threadIdx.x] - v;
    if (threadIdx.x == 1023) g_bsum[blockIdx.x] = sh[1023];
}

__global__ void k_scan2(int nb) {
    __shared__ int sh[128];
    int v = (threadIdx.x < nb) ? g_bsum[threadIdx.x] : 0;
    sh[threadIdx.x] = v;
    __syncthreads();
    for (int off = 1; off < 128; off <<= 1) {
        int t = (threadIdx.x >= off) ? sh[threadIdx.x - off] : 0;
        __syncthreads();
        sh[threadIdx.x] += t;
        __syncthreads();
    }
    if (threadIdx.x < nb) g_bsum[threadIdx.x] = sh[threadIdx.x] - v;
    if (threadIdx.x == 127) g_boff[NBK] = sh[127];
}

__global__ void k_scan3() {
    int i = blockIdx.x * 1024 + threadIdx.x;
    if (i >= NBK) return;
    int o = g_boff[i] + g_bsum[blockIdx.x];
    g_boff[i] = o;
    g_bfill[i] = o;
}

// ---------------- fill sorted edge meta ----------------
__global__ void k_fill(const void* __restrict__ idx, const void* __restrict__ mask) {
    int e = blockIdx.x * blockDim.x + threadIdx.x;
    int rel = blockIdx.y;
    if (e >= N_EDGES) return;
    if (!rd_mask(mask, rel * N_EDGES + e)) return;
    int src = rd_idx(idx, rel * 2 * N_EDGES + e);
    int dst = rd_idx(idx, rel * 2 * N_EDGES + N_EDGES + e);
    int key = (dst >> 7) * 128 + rel * 8 + ((dst >> 4) & 7);
    int pos = atomicAdd(&g_bfill[key], 1);
    g_emeta[pos] = (unsigned)src | ((unsigned)(dst & 127) << 17);
}

// ---------------- tf32-round weights ----------------
__device__ __forceinline__ unsigned f2tf(float f) {
    unsigned r;
    asm("cvt.rna.tf32.f32 %0, %1;" : "=r"(r) : "f"(f));
    return r;
}

__global__ void k_roundB(const float* __restrict__ selfw, const float* __restrict__ relw) {
    int i = blockIdx.x * blockDim.x + threadIdx.x;
    if (i >= NW * CH * CH) return;
    float v = (i < CH * CH) ? selfw[i] : relw[i - CH * CH];
    g_B[i] = __uint_as_float(f2tf(v));
}

// ---------------- fused kernel helpers ----------------
__device__ __forceinline__ void cp16(float* sdst, const float* gsrc) {
    unsigned s = (unsigned)__cvta_generic_to_shared(sdst);
    asm volatile("cp.async.cg.shared.global [%0], [%1], 16;\n" :: "r"(s), "l"(gsrc));
}

// B stage s (weight s>>2, k-chunk s&3) into ring slot s%3. mma threads (tid 0..255).
__device__ __forceinline__ void cp_stage(float* sB, int s, int tid) {
    if (s < NSTG) {
        int w = s >> 2, kt = s & 3;
        float* dB = sB + (s % 3) * 32 * BS;
        const float* src0 = g_B + (size_t)w * CH * CH + kt * 32 * CH;
#pragma unroll
        for (int i = 0; i < 4; i++) {
            int idx = tid + 256 * i;
            int kr = idx >> 5, c4 = idx & 31;
            cp16(dB + kr * BS + c4 * 4, src0 + kr * CH + c4 * 4);
        }
    }
    asm volatile("cp.async.commit_group;\n");   // commit even if empty: keeps group count uniform
}

__device__ __forceinline__ void mma4(float (*c)[4][4], const float* A, const float* Bsm,
                                     int lane) {
#pragma unroll
    for (int ks = 0; ks < 4; ks++) {
        unsigned a[4][4], b[4][2];
        int col = ks * 8 + (lane & 3);
        int r = lane >> 2;
#pragma unroll
        for (int mf = 0; mf < 4; mf++) {
            const float* Ap = A + (mf * 16 + r) * HS + col;
            a[mf][0] = f2tf(Ap[0]);
            a[mf][1] = f2tf(Ap[8 * HS]);
            a[mf][2] = f2tf(Ap[4]);
            a[mf][3] = f2tf(Ap[8 * HS + 4]);
        }
        int kr = ks * 8 + (lane & 3);
#pragma unroll
        for (int nf = 0; nf < 4; nf++) {
            const float* Bp = Bsm + kr * BS + nf * 8 + (lane >> 2);
            b[nf][0] = __float_as_uint(Bp[0]);       // pre-rounded tf32
            b[nf][1] = __float_as_uint(Bp[4 * BS]);
        }
#pragma unroll
        for (int mf = 0; mf < 4; mf++)
#pragma unroll
            for (int nf = 0; nf < 4; nf++)
                asm volatile(
                    "mma.sync.aligned.m16n8k8.row.col.f32.tf32.tf32.f32 "
                    "{%0,%1,%2,%3},{%4,%5,%6,%7},{%8,%9},{%0,%1,%2,%3};\n"
                    : "+f"(c[mf][nf][0]), "+f"(c[mf][nf][1]),
                      "+f"(c[mf][nf][2]), "+f"(c[mf][nf][3])
                    : "r"(a[mf][0]), "r"(a[mf][1]), "r"(a[mf][2]), "r"(a[mf][3]),
                      "r"(b[nf][0]), "r"(b[nf][1]));
    }
}

// gather warp gwid: rows [gwid*16, gwid*16+16) of hb = sum x[src]*invdeg, MLP-4 batched
__device__ __forceinline__ void gather_rel(const float* __restrict__ x, float* hb,
                                           int tile, int rel, int gwid, int lane) {
    float4 z = make_float4(0.f, 0.f, 0.f, 0.f);
    int r0 = gwid * 16;
#pragma unroll
    for (int r = 0; r < 16; r++)
        ((float4*)(hb + (r0 + r) * HS))[lane] = z;

    int key = tile * 128 + rel * 8 + gwid;
    int beg = g_boff[key], end = g_boff[key + 1];
    const float* vd = g_invdeg + rel * N_NODES + tile * 128;
    for (int base = beg; base < end; base += 32) {
        unsigned m = 0;
        if (base + lane < end) m = g_emeta[base + lane];
        int n = min(32, end - base);
        int j = 0;
        for (; j + 4 <= n; j += 4) {                 // 4-edge batches: MLP ~8
            int dl[4], sn[4];
            float sc[4];
            float4 v[4];
#pragma unroll
            for (int t = 0; t < 4; t++) {
                unsigned u = __shfl_sync(0xffffffffu, m, j + t);
                sn[t] = (int)(u & 0x1FFFFu);
                dl[t] = (int)(u >> 17);
            }
#pragma unroll
            for (int t = 0; t < 4; t++) sc[t] = __ldg(vd + dl[t]);
#pragma unroll
            for (int t = 0; t < 4; t++)
                v[t] = __ldg((const float4*)(x + (size_t)sn[t] * CH) + lane);
#pragma unroll
            for (int t = 0; t < 4; t++) {
                float4* hp = (float4*)(hb + dl[t] * HS) + lane;
                float4 hv = *hp;
                hv.x += v[t].x * sc[t]; hv.y += v[t].y * sc[t];
                hv.z += v[t].z * sc[t]; hv.w += v[t].w * sc[t];
                *hp = hv;
            }
        }
        for (; j < n; j++) {
            unsigned u = __shfl_sync(0xffffffffu, m, j);
            int sn = (int)(u & 0x1FFFFu);
            int dl = (int)(u >> 17);
            float s = __ldg(vd + dl);
            float4 v = __ldg((const float4*)(x + (size_t)sn * CH) + lane);
            float4* hp = (float4*)(hb + dl * HS) + lane;
            float4 hv = *hp;
            hv.x += v.x * s; hv.y += v.y * s; hv.z += v.z * s; hv.w += v.w * s;
            *hp = hv;
        }
    }
}

// ---------------- fused: warp-specialized (warps 0-7 mma, 8-15 gather) ---
__global__ __launch_bounds__(512, 1) void k_fused(const float* __restrict__ x,
                                                  float* __restrict__ out) {
    extern __shared__ float sm[];
    float* hA = sm;                 // 2 buffers
    float* sB = sm + SMF_B;         // 3-slot ring
    int tid = threadIdx.x, wid = tid >> 5, lane = tid & 31;
    int tile = blockIdx.x, bM = tile * 128;
    bool is_mma = (wid < 8);

    float c[4][4][4];
#pragma unroll
    for (int i = 0; i < 4; i++)
#pragma unroll
        for (int j = 0; j < 4; j++)
#pragma unroll
            for (int k = 0; k < 4; k++) c[i][j][k] = 0.f;

    if (is_mma) {
        cp_stage(sB, 0, tid);
        cp_stage(sB, 1, tid);
    } else {
        // self tile (weight 0) = x rows -> hA[0]
        int gwid = wid - 8, r0 = gwid * 16;
        float* hb = hA + SMF_HA0;
#pragma unroll
        for (int r = 0; r < 16; r++) {
            int rg = bM + r0 + r;
            float4 v = make_float4(0.f, 0.f, 0.f, 0.f);
            if (rg < N_NODES) v = __ldg((const float4*)(x + (size_t)rg * CH) + lane);
            ((float4*)(hb + (r0 + r) * HS))[lane] = v;
        }
    }
    __syncthreads();   // hA[0] ready

#pragma unroll 1
    for (int w = 0; w < NW; w++) {
        if (is_mma) {
            int wm = wid >> 2, wn = wid & 3;     // 2x4 warp grid over 128x128
            const float* A = hA + (w & 1) * HSZ + (wm * 64) * HS;
#pragma unroll 1
            for (int kt = 0; kt < 4; kt++) {
                int s = w * 4 + kt;
                asm volatile("cp.async.wait_group 1;\n");     // stage s landed (s+1 may fly)
                asm volatile("bar.sync 1, 256;\n" ::: "memory");  // all mma threads' copies done
                cp_stage(sB, s + 2, tid);        // overwrites slot (s-1)%3: readers done at bar
                mma4(c, A + kt * 32, sB + (s % 3) * 32 * BS + wn * 32, lane);
            }
        } else if (w < NW - 1) {
            // build hA[(w+1)&1] for relation w while mma chews on hA[w&1]
            gather_rel(x, hA + ((w + 1) & 1) * HSZ, tile, w, wid - 8, lane);
        }
        __syncthreads();   // weight boundary: next A ready, current A free
    }

    // epilogue (mma warps own the accumulators)
    if (is_mma) {
        int wm = wid >> 2, wn = wid & 3;
#pragma unroll
        for (int mf = 0; mf < 4; mf++) {
            int r0 = bM + wm * 64 + mf * 16 + (lane >> 2);
#pragma unroll
            for (int nf = 0; nf < 4; nf++) {
                int cc = wn * 32 + nf * 8 + (lane & 3) * 2;
                if (r0 < N_NODES)
                    *(float2*)(out + (size_t)r0 * CH + cc) =
                        make_float2(c[mf][nf][0], c[mf][nf][1]);
                if (r0 + 8 < N_NODES)
                    *(float2*)(out + (size_t)(r0 + 8) * CH + cc) =
                        make_float2(c[mf][nf][2], c[mf][nf][3]);
            }
        }
    }
}

// ---------------- launch ----------------
extern "C" void kernel_launch(void* const* d_in, const int* in_sizes, int n_in,
                              void* d_out, int out_size) {
    const float* x     = (const float*)d_in[0];
    const void*  idx   = d_in[1];
    const void*  mask  = d_in[2];
    const float* selfw = (const float*)d_in[3];
    const float* relw  = (const float*)d_in[4];
    float* out = (float*)d_out;

    static int init = 0;
    size_t smem = SMEM_FLOATS * sizeof(float);   // 187392 B
    if (!init) {
        cudaFuncSetAttribute(k_fused, cudaFuncAttributeMaxDynamicSharedMemorySize, (int)smem);
        init = 1;
    }

    int nb1 = (NBK + 1023) / 1024;   // 98

    k_detect<<<1, 256>>>((const unsigned*)idx, (const unsigned char*)mask);
    k_zero_pre<<<2048, 256>>>();
    k_roundB<<<(NW * CH * CH + 255) / 256, 256>>>(selfw, relw);
    k_deg<<<dim3((N_EDGES + 255) / 256, N_REL), 256>>>(idx, mask);
    k_invdeg<<<(N_REL * N_NODES + 255) / 256, 256>>>();
    k_scan1<<<nb1, 1024>>>();
    k_scan2<<<1, 128>>>(nb1);
    k_scan3<<<nb1, 1024>>>();
    k_fill<<<dim3((N_EDGES + 255) / 256, N_REL), 256>>>(idx, mask);
    k_fused<<<NT, 512, smem>>>(x, out);
}